// round 11
// baseline (speedup 1.0000x reference)
#include <cuda_runtime.h>
#include <cuda_bf16.h>
#include <math.h>
#include <stdint.h>

// Problem dims
#define BB 32
#define NN 512
#define DD 512
#define HH 8
#define HDm 64
#define ED 2048               // E*D
#define ROWS (BB*NN)          // 16384
#define QKVW (3*DD)           // 1536
#define EPS 1e-3f

// smem pitches (uint16 elements)
#define APITCH 40    // 32 bf16 + 8 pad
#define BPITCH 136   // 128 bf16 + 8 pad
#define QP 72        // 64 bf16 + 8 pad (fused attention tiles)

// gemm double-buffer layout (uint16 elements / bytes)
#define ASZ (128*APITCH)          // 5120 elems
#define BSZ (32*BPITCH)           // 4352 elems
#define STG (2*ASZ + 2*BSZ)       // 18944 elems per stage
#define ASZB (ASZ*2)
#define BSZB (BSZ*2)
#define STGB (STG*2)              // 37888 B
#define GEMM_SMEM (2*STGB)        // 75776 B

// ---------------- device scratch ----------------
__device__ float g_H  [(size_t)ROWS*DD];
__device__ float g_QKV[(size_t)ROWS*QKVW];
__device__ float g_O  [(size_t)ROWS*DD];
__device__ float g_O2 [(size_t)ROWS*DD];
__device__ float g_ATT[(size_t)ROWS*DD];
__device__ float g_F  [(size_t)ROWS*DD];
__device__ float g_F1 [(size_t)ROWS*ED];

// ---------------- helpers ----------------
__device__ __forceinline__ uint32_t sptr(const void* p) {
    return (uint32_t)__cvta_generic_to_shared(p);
}
__device__ __forceinline__ uint32_t pk(__nv_bfloat16 a, __nv_bfloat16 b) {
    return (uint32_t)__bfloat16_as_ushort(a) | ((uint32_t)__bfloat16_as_ushort(b) << 16);
}
__device__ __forceinline__ void cvt4(float4 v, uint2& hi, uint2& lo) {
    __nv_bfloat16 h0 = __float2bfloat16(v.x), h1 = __float2bfloat16(v.y);
    __nv_bfloat16 h2 = __float2bfloat16(v.z), h3 = __float2bfloat16(v.w);
    __nv_bfloat16 l0 = __float2bfloat16(v.x - __bfloat162float(h0));
    __nv_bfloat16 l1 = __float2bfloat16(v.y - __bfloat162float(h1));
    __nv_bfloat16 l2 = __float2bfloat16(v.z - __bfloat162float(h2));
    __nv_bfloat16 l3 = __float2bfloat16(v.w - __bfloat162float(h3));
    hi = make_uint2(pk(h0, h1), pk(h2, h3));
    lo = make_uint2(pk(l0, l1), pk(l2, l3));
}
__device__ __forceinline__ void ldsm4(uint32_t* r, uint32_t addr) {
    asm volatile("ldmatrix.sync.aligned.m8n8.x4.shared.b16 {%0,%1,%2,%3},[%4];"
        : "=r"(r[0]), "=r"(r[1]), "=r"(r[2]), "=r"(r[3]) : "r"(addr));
}
__device__ __forceinline__ void ldsm4t(uint32_t* r, uint32_t addr) {
    asm volatile("ldmatrix.sync.aligned.m8n8.x4.trans.shared.b16 {%0,%1,%2,%3},[%4];"
        : "=r"(r[0]), "=r"(r[1]), "=r"(r[2]), "=r"(r[3]) : "r"(addr));
}
__device__ __forceinline__ void mma16(float* c, const uint32_t* a, const uint32_t* b) {
    asm volatile(
        "mma.sync.aligned.m16n8k16.row.col.f32.bf16.bf16.f32 "
        "{%0,%1,%2,%3},{%4,%5,%6,%7},{%8,%9},{%0,%1,%2,%3};"
        : "+f"(c[0]), "+f"(c[1]), "+f"(c[2]), "+f"(c[3])
        : "r"(a[0]), "r"(a[1]), "r"(a[2]), "r"(a[3]), "r"(b[0]), "r"(b[1]));
}
__device__ __forceinline__ void mma3(float* c, const uint32_t* ah, const uint32_t* al,
                                     const uint32_t* bh, const uint32_t* bl) {
    mma16(c, ah, bh);
    mma16(c, al, bh);
    mma16(c, ah, bl);
}
__device__ __forceinline__ float gelu_exact(float x) {
    return 0.5f * x * (1.0f + erff(x * 0.70710678118654752f));
}

// ---------------- reductions ----------------
template<int THREADS>
__device__ __forceinline__ float blockReduceSum(float v, float* sh) {
    #pragma unroll
    for (int o = 16; o > 0; o >>= 1) v += __shfl_xor_sync(0xffffffffu, v, o);
    int w = threadIdx.x >> 5;
    if ((threadIdx.x & 31) == 0) sh[w] = v;
    __syncthreads();
    if (threadIdx.x < 32) {
        float t = (threadIdx.x < THREADS/32) ? sh[threadIdx.x] : 0.f;
        #pragma unroll
        for (int o = 16; o > 0; o >>= 1) t += __shfl_xor_sync(0xffffffffu, t, o);
        if (threadIdx.x == 0) sh[0] = t;
    }
    __syncthreads();
    float r = sh[0];
    __syncthreads();
    return r;
}

// ---------------- LN kernels ----------------
__global__ void ln512_kernel(const float* __restrict__ x,
                             const float* __restrict__ g, const float* __restrict__ be,
                             float* __restrict__ out) {
    __shared__ float sh[32];
    size_t base = (size_t)blockIdx.x * DD;
    float4 v = ((const float4*)(x + base))[threadIdx.x];
    float mean = blockReduceSum<128>(v.x+v.y+v.z+v.w, sh) * (1.f/DD);
    float dx=v.x-mean, dy=v.y-mean, dz=v.z-mean, dw=v.w-mean;
    float var = blockReduceSum<128>(dx*dx+dy*dy+dz*dz+dw*dw, sh) * (1.f/DD);
    float r = rsqrtf(var + EPS);
    float4 gg = ((const float4*)g)[threadIdx.x];
    float4 bb = ((const float4*)be)[threadIdx.x];
    float4 o;
    o.x = dx*r*gg.x + bb.x; o.y = dy*r*gg.y + bb.y;
    o.z = dz*r*gg.z + bb.z; o.w = dw*r*gg.w + bb.w;
    ((float4*)(out + base))[threadIdx.x] = o;
}

__global__ void ln_post_kernel(const float* __restrict__ o, const float* __restrict__ x,
                               const float* __restrict__ gp, const float* __restrict__ bp,
                               const float* __restrict__ gf, const float* __restrict__ bf,
                               float* __restrict__ att, float* __restrict__ fout) {
    __shared__ float sh[32];
    size_t base = (size_t)blockIdx.x * DD;
    float4 v = ((const float4*)(o + base))[threadIdx.x];
    float mean = blockReduceSum<128>(v.x+v.y+v.z+v.w, sh) * (1.f/DD);
    float dx=v.x-mean, dy=v.y-mean, dz=v.z-mean, dw=v.w-mean;
    float var = blockReduceSum<128>(dx*dx+dy*dy+dz*dz+dw*dw, sh) * (1.f/DD);
    float r = rsqrtf(var + EPS);
    float4 gg = ((const float4*)gp)[threadIdx.x];
    float4 bb = ((const float4*)bp)[threadIdx.x];
    float4 xr = ((const float4*)(x + base))[threadIdx.x];
    float4 a;
    a.x = dx*r*gg.x + bb.x + xr.x; a.y = dy*r*gg.y + bb.y + xr.y;
    a.z = dz*r*gg.z + bb.z + xr.z; a.w = dw*r*gg.w + bb.w + xr.w;
    ((float4*)(att + base))[threadIdx.x] = a;
    float mean2 = blockReduceSum<128>(a.x+a.y+a.z+a.w, sh) * (1.f/DD);
    float ex=a.x-mean2, ey=a.y-mean2, ez=a.z-mean2, ew=a.w-mean2;
    float var2 = blockReduceSum<128>(ex*ex+ey*ey+ez*ez+ew*ew, sh) * (1.f/DD);
    float r2 = rsqrtf(var2 + EPS);
    float4 g2 = ((const float4*)gf)[threadIdx.x];
    float4 b2 = ((const float4*)bf)[threadIdx.x];
    float4 f;
    f.x = ex*r2*g2.x + b2.x; f.y = ey*r2*g2.y + b2.y;
    f.z = ez*r2*g2.z + b2.z; f.w = ew*r2*g2.w + b2.w;
    ((float4*)(fout + base))[threadIdx.x] = f;
}

__global__ void ln_mid_kernel(float* __restrict__ f,
                              const float* __restrict__ g, const float* __restrict__ be) {
    __shared__ float sh[32];
    size_t base = (size_t)blockIdx.x * ED;
    float4* p = (float4*)(f + base);
    float4 v[4];
    float s = 0.f;
    #pragma unroll
    for (int i = 0; i < 4; i++) {
        v[i] = p[threadIdx.x + i*128];
        s += v[i].x + v[i].y + v[i].z + v[i].w;
    }
    float mean = blockReduceSum<128>(s, sh) * (1.f/ED);
    float q = 0.f;
    #pragma unroll
    for (int i = 0; i < 4; i++) {
        float a=v[i].x-mean, b=v[i].y-mean, c=v[i].z-mean, d=v[i].w-mean;
        q += a*a + b*b + c*c + d*d;
    }
    float var = blockReduceSum<128>(q, sh) * (1.f/ED);
    float r = rsqrtf(var + EPS);
    #pragma unroll
    for (int i = 0; i < 4; i++) {
        float4 gg = ((const float4*)g)[threadIdx.x + i*128];
        float4 bb = ((const float4*)be)[threadIdx.x + i*128];
        float4 o;
        o.x = (v[i].x-mean)*r*gg.x + bb.x; o.y = (v[i].y-mean)*r*gg.y + bb.y;
        o.z = (v[i].z-mean)*r*gg.z + bb.z; o.w = (v[i].w-mean)*r*gg.w + bb.w;
        p[threadIdx.x + i*128] = o;
    }
}

// ---------------- bf16x3 GEMM, 2-stage double-buffered ----------------
// Block 128x128, BK=32, 256 threads, 8 warps (2x4), warp tile 64x32.
// Dynamic smem: 2 stages x (Ah,Al,Bh,Bl).
template<int EPI>
__global__ void __launch_bounds__(256)
gemm_bf3(const float* __restrict__ A, const float* __restrict__ Bm,
         const float* __restrict__ bias, const float* __restrict__ res,
         float* __restrict__ C, int K, int lda, int ldb, int ldc) {
    extern __shared__ __align__(16) uint16_t smem[];
    const int tid = threadIdx.x, lane = tid & 31, warp = tid >> 5;
    const int wm = (warp >> 2) * 64, wn = (warp & 3) * 32;
    const int m0 = blockIdx.y * 128, n0 = blockIdx.x * 128;

    const int a_r = tid >> 1, a_c0 = (tid & 1) * 16;
    const int b_r = tid >> 3, b_c0 = (tid & 7) * 16;

    const uint32_t dynB = sptr(smem);
    const int aFragOff = ((lane & 15) * APITCH) * 2 + (lane >> 4) * 16;
    const int bKrow = (lane & 7) + ((lane >> 3) & 1) * 8;
    const int bNoff = (lane >> 4) * 8;

    float acc[4][4][4];
    #pragma unroll
    for (int i = 0; i < 4; i++)
        #pragma unroll
        for (int j = 0; j < 4; j++)
            #pragma unroll
            for (int q = 0; q < 4; q++) acc[i][j][q] = 0.f;

    // preload + fill stage 0
    float4 pa[4], pb[4];
    #pragma unroll
    for (int q = 0; q < 4; q++) {
        pa[q] = *(const float4*)(A + (size_t)(m0 + a_r) * lda + a_c0 + q*4);
        pb[q] = *(const float4*)(Bm + (size_t)b_r * ldb + n0 + b_c0 + q*4);
    }
    {
        uint16_t* stAh = smem;
        uint16_t* stAl = stAh + ASZ;
        uint16_t* stBh = stAl + ASZ;
        uint16_t* stBl = stBh + BSZ;
        #pragma unroll
        for (int q = 0; q < 4; q++) {
            uint2 hi, lo;
            cvt4(pa[q], hi, lo);
            *(uint2*)&stAh[a_r*APITCH + a_c0 + q*4] = hi;
            *(uint2*)&stAl[a_r*APITCH + a_c0 + q*4] = lo;
            cvt4(pb[q], hi, lo);
            *(uint2*)&stBh[b_r*BPITCH + b_c0 + q*4] = hi;
            *(uint2*)&stBl[b_r*BPITCH + b_c0 + q*4] = lo;
        }
    }
    __syncthreads();

    int cur = 0;
    for (int k0 = 0; k0 < K; k0 += 32) {
        const bool has_next = (k0 + 32 < K);
        if (has_next) {
            #pragma unroll
            for (int q = 0; q < 4; q++) {
                pa[q] = *(const float4*)(A + (size_t)(m0 + a_r) * lda + k0 + 32 + a_c0 + q*4);
                pb[q] = *(const float4*)(Bm + (size_t)(k0 + 32 + b_r) * ldb + n0 + b_c0 + q*4);
            }
        }
        const uint32_t cAh = dynB + cur*STGB;
        const uint32_t cAl = cAh + ASZB;
        const uint32_t cBh = cAl + ASZB;
        const uint32_t cBl = cBh + BSZB;

        #pragma unroll
        for (int half = 0; half < 2; half++) {
            const int ks = half * 16;
            uint32_t ah[4][4], al[4][4];
            #pragma unroll
            for (int mf = 0; mf < 4; mf++) {
                int off = ((wm + mf*16) * APITCH + ks) * 2 + aFragOff;
                ldsm4(ah[mf], cAh + off);
                ldsm4(al[mf], cAl + off);
            }
            uint32_t bh[4][2], bl[4][2];
            #pragma unroll
            for (int p = 0; p < 2; p++) {
                int off = ((ks + bKrow) * BPITCH + wn + p*16 + bNoff) * 2;
                uint32_t t[4];
                ldsm4t(t, cBh + off);
                bh[2*p][0]=t[0]; bh[2*p][1]=t[1]; bh[2*p+1][0]=t[2]; bh[2*p+1][1]=t[3];
                ldsm4t(t, cBl + off);
                bl[2*p][0]=t[0]; bl[2*p][1]=t[1]; bl[2*p+1][0]=t[2]; bl[2*p+1][1]=t[3];
            }
            #pragma unroll
            for (int nf = 0; nf < 4; nf++)
                #pragma unroll
                for (int mf = 0; mf < 4; mf++)
                    mma3(acc[mf][nf], ah[mf], al[mf], bh[nf], bl[nf]);

            // inject the next-stage fill between the two MMA chunks
            if (half == 0 && has_next) {
                uint16_t* stAh = smem + (cur^1)*STG;
                uint16_t* stAl = stAh + ASZ;
                uint16_t* stBh = stAl + ASZ;
                uint16_t* stBl = stBh + BSZ;
                #pragma unroll
                for (int q = 0; q < 4; q++) {
                    uint2 hi, lo;
                    cvt4(pa[q], hi, lo);
                    *(uint2*)&stAh[a_r*APITCH + a_c0 + q*4] = hi;
                    *(uint2*)&stAl[a_r*APITCH + a_c0 + q*4] = lo;
                    cvt4(pb[q], hi, lo);
                    *(uint2*)&stBh[b_r*BPITCH + b_c0 + q*4] = hi;
                    *(uint2*)&stBl[b_r*BPITCH + b_c0 + q*4] = lo;
                }
            }
        }
        __syncthreads();
        cur ^= 1;
    }

    const int r = lane >> 2, cq = lane & 3;
    #pragma unroll
    for (int mf = 0; mf < 4; mf++) {
        #pragma unroll
        for (int nf = 0; nf < 4; nf++) {
            int row = m0 + wm + mf*16 + r;
            int col = n0 + wn + nf*8 + cq*2;
            float b0v = bias[col], b1v = bias[col+1];
            float v0 = acc[mf][nf][0] + b0v, v1 = acc[mf][nf][1] + b1v;
            float v2 = acc[mf][nf][2] + b0v, v3 = acc[mf][nf][3] + b1v;
            if (EPI == 2) {
                v0 = gelu_exact(v0); v1 = gelu_exact(v1);
                v2 = gelu_exact(v2); v3 = gelu_exact(v3);
            }
            size_t o0 = (size_t)row*ldc + col;
            size_t o1 = (size_t)(row+8)*ldc + col;
            if (EPI == 3) { v0 += res[o0]; v1 += res[o0+1]; v2 += res[o1]; v3 += res[o1+1]; }
            *(float2*)&C[o0] = make_float2(v0, v1);
            *(float2*)&C[o1] = make_float2(v2, v3);
        }
    }
}

// ---------------- fused flash attention (unchanged from 2031us version) ----------------
__global__ void __launch_bounds__(256)
attn_fused(const float* __restrict__ qkv, const float* __restrict__ inter,
           const int* __restrict__ mask, float* __restrict__ O) {
    extern __shared__ __align__(16) uint16_t dyn[];
    uint16_t* sKh = dyn;
    uint16_t* sKl = sKh + 128*QP;
    uint16_t* sVh = sKl + 128*QP;
    uint16_t* sVl = sVh + 128*QP;

    const int tid = threadIdx.x, lane = tid & 31, warp = tid >> 5;
    const int bh = blockIdx.y, b = bh >> 3, h = bh & 7;
    const int n0 = blockIdx.x * 128;
    const int r = lane >> 2, cq = lane & 3;
    const float* Qb = qkv + (size_t)b*NN*QKVW + h*HDm;
    const float* Kb = Qb + DD;
    const float* Vb = Qb + 2*DD;

    const int t_r = tid >> 1, t_c0 = (tid & 1) * 32;

    const uint32_t bKh = sptr(sKh), bKl = sptr(sKl);
    const uint32_t bVh = sptr(sVh), bVl = sptr(sVl);
    const int aFragOff = ((lane & 15) * QP) * 2 + (lane >> 4) * 16;
    const int kNrow = (lane & 7) + ((lane >> 4) & 1) * 8;
    const int kByteOff = ((lane >> 3) & 1) * 16;
    const int vKrow = (lane & 7) + ((lane >> 3) & 1) * 8;
    const int vNoff = (lane >> 4) * 8;

    #pragma unroll
    for (int q = 0; q < 8; q++) {
        float4 v = *(const float4*)(Qb + (size_t)(n0 + t_r) * QKVW + t_c0 + q*4);
        uint2 hi, lo;
        cvt4(v, hi, lo);
        *(uint2*)&sKh[t_r*QP + t_c0 + q*4] = hi;
        *(uint2*)&sKl[t_r*QP + t_c0 + q*4] = lo;
    }
    __syncthreads();
    uint32_t qh[4][4], ql[4][4];
    #pragma unroll
    for (int kk = 0; kk < 4; kk++) {
        int off = ((warp*16) * QP + kk*16) * 2 + aFragOff;
        ldsm4(qh[kk], bKh + off);
        ldsm4(ql[kk], bKl + off);
    }
    __syncthreads();

    float m0 = -3.4e38f, m1 = -3.4e38f, l0 = 0.f, l1 = 0.f;
    float oacc[8][4];
    #pragma unroll
    for (int i = 0; i < 8; i++)
        #pragma unroll
        for (int q = 0; q < 4; q++) oacc[i][q] = 0.f;

    const int row0 = n0 + warp*16 + r;
    const int row1 = row0 + 8;

    for (int kt = 0; kt < 4; kt++) {
        const int k0 = kt * 128;
        #pragma unroll
        for (int q = 0; q < 8; q++) {
            float4 kv = *(const float4*)(Kb + (size_t)(k0 + t_r) * QKVW + t_c0 + q*4);
            float4 vv = *(const float4*)(Vb + (size_t)(k0 + t_r) * QKVW + t_c0 + q*4);
            uint2 hi, lo;
            cvt4(kv, hi, lo);
            *(uint2*)&sKh[t_r*QP + t_c0 + q*4] = hi;
            *(uint2*)&sKl[t_r*QP + t_c0 + q*4] = lo;
            cvt4(vv, hi, lo);
            *(uint2*)&sVh[t_r*QP + t_c0 + q*4] = hi;
            *(uint2*)&sVl[t_r*QP + t_c0 + q*4] = lo;
        }
        __syncthreads();

        float acc[16][4];
        #pragma unroll
        for (int i = 0; i < 16; i++)
            #pragma unroll
            for (int q = 0; q < 4; q++) acc[i][q] = 0.f;

        #pragma unroll
        for (int kk = 0; kk < 4; kk++) {
            #pragma unroll
            for (int p = 0; p < 8; p++) {
                int off = ((p*16 + kNrow) * QP + kk*16) * 2 + kByteOff;
                uint32_t th[4], tl[4];
                ldsm4(th, bKh + off);
                ldsm4(tl, bKl + off);
                mma3(acc[2*p  ], qh[kk], ql[kk], &th[0], &tl[0]);
                mma3(acc[2*p+1], qh[kk], ql[kk], &th[2], &tl[2]);
            }
        }

        float mx0 = -3.4e38f, mx1 = -3.4e38f;
        #pragma unroll
        for (int nf = 0; nf < 16; nf++) {
            int key = k0 + nf*8 + cq*2;
            size_t i0 = ((size_t)(b*NN + row0) * NN + key) * HH + h;
            size_t i1 = ((size_t)(b*NN + row1) * NN + key) * HH + h;
            size_t mr0 = (size_t)(b*NN + row0) * NN + key;
            size_t mr1 = (size_t)(b*NN + row1) * NN + key;
            float s0 = acc[nf][0]*0.125f + inter[i0]      + (mask[mr0]   ? 0.f : -1e9f);
            float s1 = acc[nf][1]*0.125f + inter[i0 + HH] + (mask[mr0+1] ? 0.f : -1e9f);
            float s2 = acc[nf][2]*0.125f + inter[i1]      + (mask[mr1]   ? 0.f : -1e9f);
            float s3 = acc[nf][3]*0.125f + inter[i1 + HH] + (mask[mr1+1] ? 0.f : -1e9f);
            acc[nf][0]=s0; acc[nf][1]=s1; acc[nf][2]=s2; acc[nf][3]=s3;
            mx0 = fmaxf(mx0, fmaxf(s0, s1));
            mx1 = fmaxf(mx1, fmaxf(s2, s3));
        }
        #pragma unroll
        for (int o = 1; o <= 2; o <<= 1) {
            mx0 = fmaxf(mx0, __shfl_xor_sync(0xffffffffu, mx0, o));
            mx1 = fmaxf(mx1, __shfl_xor_sync(0xffffffffu, mx1, o));
        }
        float mn0 = fmaxf(m0, mx0), mn1 = fmaxf(m1, mx1);
        float sc0 = __expf(m0 - mn0), sc1 = __expf(m1 - mn1);
        m0 = mn0; m1 = mn1;

        float sum0 = 0.f, sum1 = 0.f;
        #pragma unroll
        for (int nf = 0; nf < 16; nf++) {
            float p0 = __expf(acc[nf][0] - mn0);
            float p1 = __expf(acc[nf][1] - mn0);
            float p2 = __expf(acc[nf][2] - mn1);
            float p3 = __expf(acc[nf][3] - mn1);
            acc[nf][0]=p0; acc[nf][1]=p1; acc[nf][2]=p2; acc[nf][3]=p3;
            sum0 += p0 + p1; sum1 += p2 + p3;
        }
        #pragma unroll
        for (int o = 1; o <= 2; o <<= 1) {
            sum0 += __shfl_xor_sync(0xffffffffu, sum0, o);
            sum1 += __shfl_xor_sync(0xffffffffu, sum1, o);
        }
        l0 = l0*sc0 + sum0; l1 = l1*sc1 + sum1;

        #pragma unroll
        for (int onf = 0; onf < 8; onf++) {
            oacc[onf][0]*=sc0; oacc[onf][1]*=sc0;
            oacc[onf][2]*=sc1; oacc[onf][3]*=sc1;
        }

        #pragma unroll
        for (int g = 0; g < 8; g++) {
            uint32_t pah[4], pal[4];
            {
                float v00=acc[2*g][0], v01=acc[2*g][1], v02=acc[2*g][2], v03=acc[2*g][3];
                float w00=acc[2*g+1][0], w01=acc[2*g+1][1], w02=acc[2*g+1][2], w03=acc[2*g+1][3];
                __nv_bfloat16 h00=__float2bfloat16(v00), h01=__float2bfloat16(v01);
                __nv_bfloat16 h02=__float2bfloat16(v02), h03=__float2bfloat16(v03);
                __nv_bfloat16 k00=__float2bfloat16(w00), k01=__float2bfloat16(w01);
                __nv_bfloat16 k02=__float2bfloat16(w02), k03=__float2bfloat16(w03);
                pah[0]=pk(h00,h01); pah[1]=pk(h02,h03); pah[2]=pk(k00,k01); pah[3]=pk(k02,k03);
                pal[0]=pk(__float2bfloat16(v00-__bfloat162float(h00)),
                          __float2bfloat16(v01-__bfloat162float(h01)));
                pal[1]=pk(__float2bfloat16(v02-__bfloat162float(h02)),
                          __float2bfloat16(v03-__bfloat162float(h03)));
                pal[2]=pk(__float2bfloat16(w00-__bfloat162float(k00)),
                          __float2bfloat16(w01-__bfloat162float(k01)));
                pal[3]=pk(__float2bfloat16(w02-__bfloat162float(k02)),
                          __float2bfloat16(w03-__bfloat162float(k03)));
            }
            #pragma unroll
            for (int p = 0; p < 4; p++) {
                int off = ((g*16 + vKrow) * QP + p*16 + vNoff) * 2;
                uint32_t th[4], tl[4];
                ldsm4t(th, bVh + off);
                ldsm4t(tl, bVl + off);
                mma3(oacc[2*p  ], pah, pal, &th[0], &tl[0]);
                mma3(oacc[2*p+1], pah, pal, &th[2], &tl[2]);
            }
        }
        __syncthreads();
    }

    float inv0 = 1.f / l0, inv1 = 1.f / l1;
    #pragma unroll
    for (int onf = 0; onf < 8; onf++) {
        int col = h*HDm + onf*8 + cq*2;
        size_t o0 = (size_t)(b*NN + row0) * DD + col;
        size_t o1 = (size_t)(b*NN + row1) * DD + col;
        *(float2*)&O[o0] = make_float2(oacc[onf][0]*inv0, oacc[onf][1]*inv0);
        *(float2*)&O[o1] = make_float2(oacc[onf][2]*inv1, oacc[onf][3]*inv1);
    }
}

// ---------------- launch ----------------
extern "C" void kernel_launch(void* const* d_in, const int* in_sizes, int n_in,
                              void* d_out, int out_size) {
    const float* x      = (const float*)d_in[0];
    const int*   mask   = (const int*)  d_in[1];
    const float* inter  = (const float*)d_in[2];
    const float* w_qkv  = (const float*)d_in[3];
    const float* b_qkv  = (const float*)d_in[4];
    const float* w_out  = (const float*)d_in[5];
    const float* b_out  = (const float*)d_in[6];
    const float* w1     = (const float*)d_in[7];
    const float* b1     = (const float*)d_in[8];
    const float* w2     = (const float*)d_in[9];
    const float* b2     = (const float*)d_in[10];
    const float* g_pre  = (const float*)d_in[11];
    const float* be_pre = (const float*)d_in[12];
    const float* g_post = (const float*)d_in[13];
    const float* be_post= (const float*)d_in[14];
    const float* g_ffn  = (const float*)d_in[15];
    const float* be_ffn = (const float*)d_in[16];
    const float* g_mid  = (const float*)d_in[17];
    const float* be_mid = (const float*)d_in[18];
    float* out = (float*)d_out;

    float *H, *QKV, *O, *O2, *ATT, *F, *F1;
    cudaGetSymbolAddress((void**)&H,   g_H);
    cudaGetSymbolAddress((void**)&QKV, g_QKV);
    cudaGetSymbolAddress((void**)&O,   g_O);
    cudaGetSymbolAddress((void**)&O2,  g_O2);
    cudaGetSymbolAddress((void**)&ATT, g_ATT);
    cudaGetSymbolAddress((void**)&F,   g_F);
    cudaGetSymbolAddress((void**)&F1,  g_F1);

    static bool attr_set = false;
    if (!attr_set) {
        cudaFuncSetAttribute(attn_fused, cudaFuncAttributeMaxDynamicSharedMemorySize,
                             4*128*QP*2);
        cudaFuncSetAttribute(gemm_bf3<1>, cudaFuncAttributeMaxDynamicSharedMemorySize,
                             GEMM_SMEM);
        cudaFuncSetAttribute(gemm_bf3<2>, cudaFuncAttributeMaxDynamicSharedMemorySize,
                             GEMM_SMEM);
        cudaFuncSetAttribute(gemm_bf3<3>, cudaFuncAttributeMaxDynamicSharedMemorySize,
                             GEMM_SMEM);
        attr_set = true;
    }

    ln512_kernel<<<ROWS, 128>>>(x, g_pre, be_pre, H);
    gemm_bf3<1><<<dim3(QKVW/128, ROWS/128), 256, GEMM_SMEM>>>(H, w_qkv, b_qkv, nullptr, QKV,
                                                              DD, DD, QKVW, QKVW);
    attn_fused<<<dim3(4, BB*HH), 256, 4*128*QP*2>>>(QKV, inter, mask, O);
    gemm_bf3<1><<<dim3(DD/128, ROWS/128), 256, GEMM_SMEM>>>(O, w_out, b_out, nullptr, O2,
                                                            DD, DD, DD, DD);
    ln_post_kernel<<<ROWS, 128>>>(O2, x, g_post, be_post, g_ffn, be_ffn, ATT, F);
    gemm_bf3<2><<<dim3(ED/128, ROWS/128), 256, GEMM_SMEM>>>(F, w1, b1, nullptr, F1,
                                                            DD, DD, ED, ED);
    ln_mid_kernel<<<ROWS, 128>>>(F1, g_mid, be_mid);
    gemm_bf3<3><<<dim3(DD/128, ROWS/128), 256, GEMM_SMEM>>>(F1, w2, b2, ATT, out,
                                                            ED, ED, DD, DD);
}

// round 16
// speedup vs baseline: 1.0946x; 1.0946x over previous
#include <cuda_runtime.h>
#include <cuda_bf16.h>
#include <math.h>
#include <stdint.h>

// Problem dims
#define BB 32
#define NN 512
#define DD 512
#define HH 8
#define HDm 64
#define ED 2048               // E*D
#define ROWS (BB*NN)          // 16384
#define QKVW (3*DD)           // 1536
#define EPS 1e-3f

// smem pitches (uint16 elements)
#define APITCH 40    // 32 bf16 + 8 pad
#define BPITCH 136   // 128 bf16 + 8 pad
#define QP 72        // 64 bf16 + 8 pad (fused attention tiles)

// ---------------- device scratch ----------------
__device__ float g_H  [(size_t)ROWS*DD];
__device__ float g_QKV[(size_t)ROWS*QKVW];
__device__ float g_IT [(size_t)BB*HH*NN*NN];   // transposed interaction + mask folded
__device__ float g_O  [(size_t)ROWS*DD];
__device__ float g_O2 [(size_t)ROWS*DD];
__device__ float g_ATT[(size_t)ROWS*DD];
__device__ float g_F  [(size_t)ROWS*DD];
__device__ float g_F1 [(size_t)ROWS*ED];

// ---------------- helpers ----------------
__device__ __forceinline__ uint32_t sptr(const void* p) {
    return (uint32_t)__cvta_generic_to_shared(p);
}
__device__ __forceinline__ uint32_t pk(__nv_bfloat16 a, __nv_bfloat16 b) {
    return (uint32_t)__bfloat16_as_ushort(a) | ((uint32_t)__bfloat16_as_ushort(b) << 16);
}
__device__ __forceinline__ void cvt4(float4 v, uint2& hi, uint2& lo) {
    __nv_bfloat16 h0 = __float2bfloat16(v.x), h1 = __float2bfloat16(v.y);
    __nv_bfloat16 h2 = __float2bfloat16(v.z), h3 = __float2bfloat16(v.w);
    __nv_bfloat16 l0 = __float2bfloat16(v.x - __bfloat162float(h0));
    __nv_bfloat16 l1 = __float2bfloat16(v.y - __bfloat162float(h1));
    __nv_bfloat16 l2 = __float2bfloat16(v.z - __bfloat162float(h2));
    __nv_bfloat16 l3 = __float2bfloat16(v.w - __bfloat162float(h3));
    hi = make_uint2(pk(h0, h1), pk(h2, h3));
    lo = make_uint2(pk(l0, l1), pk(l2, l3));
}
__device__ __forceinline__ void ldsm4(uint32_t* r, uint32_t addr) {
    asm volatile("ldmatrix.sync.aligned.m8n8.x4.shared.b16 {%0,%1,%2,%3},[%4];"
        : "=r"(r[0]), "=r"(r[1]), "=r"(r[2]), "=r"(r[3]) : "r"(addr));
}
__device__ __forceinline__ void ldsm4t(uint32_t* r, uint32_t addr) {
    asm volatile("ldmatrix.sync.aligned.m8n8.x4.trans.shared.b16 {%0,%1,%2,%3},[%4];"
        : "=r"(r[0]), "=r"(r[1]), "=r"(r[2]), "=r"(r[3]) : "r"(addr));
}
__device__ __forceinline__ void mma16(float* c, const uint32_t* a, const uint32_t* b) {
    asm volatile(
        "mma.sync.aligned.m16n8k16.row.col.f32.bf16.bf16.f32 "
        "{%0,%1,%2,%3},{%4,%5,%6,%7},{%8,%9},{%0,%1,%2,%3};"
        : "+f"(c[0]), "+f"(c[1]), "+f"(c[2]), "+f"(c[3])
        : "r"(a[0]), "r"(a[1]), "r"(a[2]), "r"(a[3]), "r"(b[0]), "r"(b[1]));
}
__device__ __forceinline__ void mma3(float* c, const uint32_t* ah, const uint32_t* al,
                                     const uint32_t* bh, const uint32_t* bl) {
    mma16(c, ah, bh);
    mma16(c, al, bh);
    mma16(c, ah, bl);
}
__device__ __forceinline__ float gelu_exact(float x) {
    return 0.5f * x * (1.0f + erff(x * 0.70710678118654752f));
}

// ---------------- reductions ----------------
template<int THREADS>
__device__ __forceinline__ float blockReduceSum(float v, float* sh) {
    #pragma unroll
    for (int o = 16; o > 0; o >>= 1) v += __shfl_xor_sync(0xffffffffu, v, o);
    int w = threadIdx.x >> 5;
    if ((threadIdx.x & 31) == 0) sh[w] = v;
    __syncthreads();
    if (threadIdx.x < 32) {
        float t = (threadIdx.x < THREADS/32) ? sh[threadIdx.x] : 0.f;
        #pragma unroll
        for (int o = 16; o > 0; o >>= 1) t += __shfl_xor_sync(0xffffffffu, t, o);
        if (threadIdx.x == 0) sh[0] = t;
    }
    __syncthreads();
    float r = sh[0];
    __syncthreads();
    return r;
}

// ---------------- interaction transpose + mask fold ----------------
// IT[b][h][q][k] = inter[b][q][k][h] + (mask[b][q][k] ? 0 : -1e9)
// block per (q, b): 512 k x 8 h tile. 256 threads.
__global__ void inter_tr_kernel(const float* __restrict__ inter,
                                const int* __restrict__ mask,
                                float* __restrict__ IT) {
    __shared__ float s[NN * 9];   // padded: s[k*9 + h], conflict-free on read
    const int q = blockIdx.x, b = blockIdx.y;
    const float4* src4 = (const float4*)(inter + ((size_t)(b*NN + q) * NN) * HH);
    // load 4096 floats = 1024 float4; float4 i covers k=i>>1, h=(i&1)*4..+3
    // NOTE: scalar smem stores (pitch 9 breaks 16B alignment for vector stores)
    #pragma unroll
    for (int i = threadIdx.x; i < NN*HH/4; i += 256) {
        int k = i >> 1, h4 = (i & 1) * 4;
        float4 v = src4[i];
        s[k*9 + h4 + 0] = v.x;
        s[k*9 + h4 + 1] = v.y;
        s[k*9 + h4 + 2] = v.z;
        s[k*9 + h4 + 3] = v.w;
    }
    __syncthreads();
    const int* mrow = mask + (size_t)(b*NN + q) * NN;
    // write: i = h*NN + k, consecutive i -> consecutive k (coalesced)
    #pragma unroll
    for (int i = threadIdx.x; i < NN*HH; i += 256) {
        int h = i >> 9, k = i & (NN-1);
        float v = s[k*9 + h] + (mrow[k] ? 0.f : -1e9f);
        IT[(((size_t)(b*HH + h)) * NN + q) * NN + k] = v;
    }
}

// ---------------- LN kernels ----------------
__global__ void ln512_kernel(const float* __restrict__ x,
                             const float* __restrict__ g, const float* __restrict__ be,
                             float* __restrict__ out) {
    __shared__ float sh[32];
    size_t base = (size_t)blockIdx.x * DD;
    float4 v = ((const float4*)(x + base))[threadIdx.x];
    float mean = blockReduceSum<128>(v.x+v.y+v.z+v.w, sh) * (1.f/DD);
    float dx=v.x-mean, dy=v.y-mean, dz=v.z-mean, dw=v.w-mean;
    float var = blockReduceSum<128>(dx*dx+dy*dy+dz*dz+dw*dw, sh) * (1.f/DD);
    float r = rsqrtf(var + EPS);
    float4 gg = ((const float4*)g)[threadIdx.x];
    float4 bb = ((const float4*)be)[threadIdx.x];
    float4 o;
    o.x = dx*r*gg.x + bb.x; o.y = dy*r*gg.y + bb.y;
    o.z = dz*r*gg.z + bb.z; o.w = dw*r*gg.w + bb.w;
    ((float4*)(out + base))[threadIdx.x] = o;
}

__global__ void ln_post_kernel(const float* __restrict__ o, const float* __restrict__ x,
                               const float* __restrict__ gp, const float* __restrict__ bp,
                               const float* __restrict__ gf, const float* __restrict__ bf,
                               float* __restrict__ att, float* __restrict__ fout) {
    __shared__ float sh[32];
    size_t base = (size_t)blockIdx.x * DD;
    float4 v = ((const float4*)(o + base))[threadIdx.x];
    float mean = blockReduceSum<128>(v.x+v.y+v.z+v.w, sh) * (1.f/DD);
    float dx=v.x-mean, dy=v.y-mean, dz=v.z-mean, dw=v.w-mean;
    float var = blockReduceSum<128>(dx*dx+dy*dy+dz*dz+dw*dw, sh) * (1.f/DD);
    float r = rsqrtf(var + EPS);
    float4 gg = ((const float4*)gp)[threadIdx.x];
    float4 bb = ((const float4*)bp)[threadIdx.x];
    float4 xr = ((const float4*)(x + base))[threadIdx.x];
    float4 a;
    a.x = dx*r*gg.x + bb.x + xr.x; a.y = dy*r*gg.y + bb.y + xr.y;
    a.z = dz*r*gg.z + bb.z + xr.z; a.w = dw*r*gg.w + bb.w + xr.w;
    ((float4*)(att + base))[threadIdx.x] = a;
    float mean2 = blockReduceSum<128>(a.x+a.y+a.z+a.w, sh) * (1.f/DD);
    float ex=a.x-mean2, ey=a.y-mean2, ez=a.z-mean2, ew=a.w-mean2;
    float var2 = blockReduceSum<128>(ex*ex+ey*ey+ez*ez+ew*ew, sh) * (1.f/DD);
    float r2 = rsqrtf(var2 + EPS);
    float4 g2 = ((const float4*)gf)[threadIdx.x];
    float4 b2 = ((const float4*)bf)[threadIdx.x];
    float4 f;
    f.x = ex*r2*g2.x + b2.x; f.y = ey*r2*g2.y + b2.y;
    f.z = ez*r2*g2.z + b2.z; f.w = ew*r2*g2.w + b2.w;
    ((float4*)(fout + base))[threadIdx.x] = f;
}

__global__ void ln_mid_kernel(float* __restrict__ f,
                              const float* __restrict__ g, const float* __restrict__ be) {
    __shared__ float sh[32];
    size_t base = (size_t)blockIdx.x * ED;
    float4* p = (float4*)(f + base);
    float4 v[4];
    float s = 0.f;
    #pragma unroll
    for (int i = 0; i < 4; i++) {
        v[i] = p[threadIdx.x + i*128];
        s += v[i].x + v[i].y + v[i].z + v[i].w;
    }
    float mean = blockReduceSum<128>(s, sh) * (1.f/ED);
    float q = 0.f;
    #pragma unroll
    for (int i = 0; i < 4; i++) {
        float a=v[i].x-mean, b=v[i].y-mean, c=v[i].z-mean, d=v[i].w-mean;
        q += a*a + b*b + c*c + d*d;
    }
    float var = blockReduceSum<128>(q, sh) * (1.f/ED);
    float r = rsqrtf(var + EPS);
    #pragma unroll
    for (int i = 0; i < 4; i++) {
        float4 gg = ((const float4*)g)[threadIdx.x + i*128];
        float4 bb = ((const float4*)be)[threadIdx.x + i*128];
        float4 o;
        o.x = (v[i].x-mean)*r*gg.x + bb.x; o.y = (v[i].y-mean)*r*gg.y + bb.y;
        o.z = (v[i].z-mean)*r*gg.z + bb.z; o.w = (v[i].w-mean)*r*gg.w + bb.w;
        p[threadIdx.x + i*128] = o;
    }
}

// ---------------- bf16x3 GEMM (identical to the 2031us version) ----------------
template<int EPI>
__global__ void __launch_bounds__(256)
gemm_bf3(const float* __restrict__ A, const float* __restrict__ Bm,
         const float* __restrict__ bias, const float* __restrict__ res,
         float* __restrict__ C, int K, int lda, int ldb, int ldc) {
    __shared__ __align__(16) uint16_t sAh[128*APITCH], sAl[128*APITCH];
    __shared__ __align__(16) uint16_t sBh[32*BPITCH],  sBl[32*BPITCH];
    const int tid = threadIdx.x, lane = tid & 31, warp = tid >> 5;
    const int wm = (warp >> 2) * 64, wn = (warp & 3) * 32;
    const int m0 = blockIdx.y * 128, n0 = blockIdx.x * 128;

    const int a_r = tid >> 1, a_c0 = (tid & 1) * 16;
    const int b_r = tid >> 3, b_c0 = (tid & 7) * 16;

    float4 pa[4], pb[4];
    #pragma unroll
    for (int q = 0; q < 4; q++) {
        pa[q] = *(const float4*)(A + (size_t)(m0 + a_r) * lda + a_c0 + q*4);
        pb[q] = *(const float4*)(Bm + (size_t)b_r * ldb + n0 + b_c0 + q*4);
    }

    float acc[4][4][4];
    #pragma unroll
    for (int i = 0; i < 4; i++)
        #pragma unroll
        for (int j = 0; j < 4; j++)
            #pragma unroll
            for (int q = 0; q < 4; q++) acc[i][j][q] = 0.f;

    const uint32_t baseAh = sptr(sAh), baseAl = sptr(sAl);
    const uint32_t baseBh = sptr(sBh), baseBl = sptr(sBl);
    const int aFragOff = ((lane & 15) * APITCH) * 2 + (lane >> 4) * 16;
    const int bKrow = (lane & 7) + ((lane >> 3) & 1) * 8;
    const int bNoff = (lane >> 4) * 8;

    for (int k0 = 0; k0 < K; k0 += 32) {
        #pragma unroll
        for (int q = 0; q < 4; q++) {
            uint2 hi, lo;
            cvt4(pa[q], hi, lo);
            *(uint2*)&sAh[a_r*APITCH + a_c0 + q*4] = hi;
            *(uint2*)&sAl[a_r*APITCH + a_c0 + q*4] = lo;
            cvt4(pb[q], hi, lo);
            *(uint2*)&sBh[b_r*BPITCH + b_c0 + q*4] = hi;
            *(uint2*)&sBl[b_r*BPITCH + b_c0 + q*4] = lo;
        }
        __syncthreads();
        if (k0 + 32 < K) {
            #pragma unroll
            for (int q = 0; q < 4; q++) {
                pa[q] = *(const float4*)(A + (size_t)(m0 + a_r) * lda + k0 + 32 + a_c0 + q*4);
                pb[q] = *(const float4*)(Bm + (size_t)(k0 + 32 + b_r) * ldb + n0 + b_c0 + q*4);
            }
        }
        #pragma unroll
        for (int ks = 0; ks < 32; ks += 16) {
            uint32_t ah[4][4], al[4][4];
            #pragma unroll
            for (int mf = 0; mf < 4; mf++) {
                int off = ((wm + mf*16) * APITCH + ks) * 2 + aFragOff;
                ldsm4(ah[mf], baseAh + off);
                ldsm4(al[mf], baseAl + off);
            }
            uint32_t bh[4][2], bl[4][2];
            #pragma unroll
            for (int p = 0; p < 2; p++) {
                int off = ((ks + bKrow) * BPITCH + wn + p*16 + bNoff) * 2;
                uint32_t t[4];
                ldsm4t(t, baseBh + off);
                bh[2*p][0]=t[0]; bh[2*p][1]=t[1]; bh[2*p+1][0]=t[2]; bh[2*p+1][1]=t[3];
                ldsm4t(t, baseBl + off);
                bl[2*p][0]=t[0]; bl[2*p][1]=t[1]; bl[2*p+1][0]=t[2]; bl[2*p+1][1]=t[3];
            }
            #pragma unroll
            for (int nf = 0; nf < 4; nf++)
                #pragma unroll
                for (int mf = 0; mf < 4; mf++)
                    mma3(acc[mf][nf], ah[mf], al[mf], bh[nf], bl[nf]);
        }
        __syncthreads();
    }

    const int r = lane >> 2, cq = lane & 3;
    #pragma unroll
    for (int mf = 0; mf < 4; mf++) {
        #pragma unroll
        for (int nf = 0; nf < 4; nf++) {
            int row = m0 + wm + mf*16 + r;
            int col = n0 + wn + nf*8 + cq*2;
            float b0v = bias[col], b1v = bias[col+1];
            float v0 = acc[mf][nf][0] + b0v, v1 = acc[mf][nf][1] + b1v;
            float v2 = acc[mf][nf][2] + b0v, v3 = acc[mf][nf][3] + b1v;
            if (EPI == 2) {
                v0 = gelu_exact(v0); v1 = gelu_exact(v1);
                v2 = gelu_exact(v2); v3 = gelu_exact(v3);
            }
            size_t o0 = (size_t)row*ldc + col;
            size_t o1 = (size_t)(row+8)*ldc + col;
            if (EPI == 3) { v0 += res[o0]; v1 += res[o0+1]; v2 += res[o1]; v3 += res[o1+1]; }
            *(float2*)&C[o0] = make_float2(v0, v1);
            *(float2*)&C[o1] = make_float2(v2, v3);
        }
    }
}

// ---------------- fused flash attention (reads pre-transposed IT) ----------------
__global__ void __launch_bounds__(256)
attn_fused(const float* __restrict__ qkv, const float* __restrict__ IT,
           float* __restrict__ O) {
    extern __shared__ __align__(16) uint16_t dyn[];
    uint16_t* sKh = dyn;
    uint16_t* sKl = sKh + 128*QP;
    uint16_t* sVh = sKl + 128*QP;
    uint16_t* sVl = sVh + 128*QP;

    const int tid = threadIdx.x, lane = tid & 31, warp = tid >> 5;
    const int bh = blockIdx.y, b = bh >> 3, h = bh & 7;
    const int n0 = blockIdx.x * 128;
    const int r = lane >> 2, cq = lane & 3;
    const float* Qb = qkv + (size_t)b*NN*QKVW + h*HDm;
    const float* Kb = Qb + DD;
    const float* Vb = Qb + 2*DD;
    const float* ITb = IT + (size_t)bh * NN * NN;

    const int t_r = tid >> 1, t_c0 = (tid & 1) * 32;

    const uint32_t bKh = sptr(sKh), bKl = sptr(sKl);
    const uint32_t bVh = sptr(sVh), bVl = sptr(sVl);
    const int aFragOff = ((lane & 15) * QP) * 2 + (lane >> 4) * 16;
    const int kNrow = (lane & 7) + ((lane >> 4) & 1) * 8;
    const int kByteOff = ((lane >> 3) & 1) * 16;
    const int vKrow = (lane & 7) + ((lane >> 3) & 1) * 8;
    const int vNoff = (lane >> 4) * 8;

    #pragma unroll
    for (int q = 0; q < 8; q++) {
        float4 v = *(const float4*)(Qb + (size_t)(n0 + t_r) * QKVW + t_c0 + q*4);
        uint2 hi, lo;
        cvt4(v, hi, lo);
        *(uint2*)&sKh[t_r*QP + t_c0 + q*4] = hi;
        *(uint2*)&sKl[t_r*QP + t_c0 + q*4] = lo;
    }
    __syncthreads();
    uint32_t qh[4][4], ql[4][4];
    #pragma unroll
    for (int kk = 0; kk < 4; kk++) {
        int off = ((warp*16) * QP + kk*16) * 2 + aFragOff;
        ldsm4(qh[kk], bKh + off);
        ldsm4(ql[kk], bKl + off);
    }
    __syncthreads();

    float m0 = -3.4e38f, m1 = -3.4e38f, l0 = 0.f, l1 = 0.f;
    float oacc[8][4];
    #pragma unroll
    for (int i = 0; i < 8; i++)
        #pragma unroll
        for (int q = 0; q < 4; q++) oacc[i][q] = 0.f;

    const int row0 = n0 + warp*16 + r;
    const int row1 = row0 + 8;

    for (int kt = 0; kt < 4; kt++) {
        const int k0 = kt * 128;
        #pragma unroll
        for (int q = 0; q < 8; q++) {
            float4 kv = *(const float4*)(Kb + (size_t)(k0 + t_r) * QKVW + t_c0 + q*4);
            float4 vv = *(const float4*)(Vb + (size_t)(k0 + t_r) * QKVW + t_c0 + q*4);
            uint2 hi, lo;
            cvt4(kv, hi, lo);
            *(uint2*)&sKh[t_r*QP + t_c0 + q*4] = hi;
            *(uint2*)&sKl[t_r*QP + t_c0 + q*4] = lo;
            cvt4(vv, hi, lo);
            *(uint2*)&sVh[t_r*QP + t_c0 + q*4] = hi;
            *(uint2*)&sVl[t_r*QP + t_c0 + q*4] = lo;
        }
        __syncthreads();

        float acc[16][4];
        #pragma unroll
        for (int i = 0; i < 16; i++)
            #pragma unroll
            for (int q = 0; q < 4; q++) acc[i][q] = 0.f;

        #pragma unroll
        for (int kk = 0; kk < 4; kk++) {
            #pragma unroll
            for (int p = 0; p < 8; p++) {
                int off = ((p*16 + kNrow) * QP + kk*16) * 2 + kByteOff;
                uint32_t th[4], tl[4];
                ldsm4(th, bKh + off);
                ldsm4(tl, bKl + off);
                mma3(acc[2*p  ], qh[kk], ql[kk], &th[0], &tl[0]);
                mma3(acc[2*p+1], qh[kk], ql[kk], &th[2], &tl[2]);
            }
        }

        float mx0 = -3.4e38f, mx1 = -3.4e38f;
        #pragma unroll
        for (int nf = 0; nf < 16; nf++) {
            int key = k0 + nf*8 + cq*2;
            float2 iv0 = *(const float2*)&ITb[(size_t)row0 * NN + key];
            float2 iv1 = *(const float2*)&ITb[(size_t)row1 * NN + key];
            float s0 = acc[nf][0]*0.125f + iv0.x;
            float s1 = acc[nf][1]*0.125f + iv0.y;
            float s2 = acc[nf][2]*0.125f + iv1.x;
            float s3 = acc[nf][3]*0.125f + iv1.y;
            acc[nf][0]=s0; acc[nf][1]=s1; acc[nf][2]=s2; acc[nf][3]=s3;
            mx0 = fmaxf(mx0, fmaxf(s0, s1));
            mx1 = fmaxf(mx1, fmaxf(s2, s3));
        }
        #pragma unroll
        for (int o = 1; o <= 2; o <<= 1) {
            mx0 = fmaxf(mx0, __shfl_xor_sync(0xffffffffu, mx0, o));
            mx1 = fmaxf(mx1, __shfl_xor_sync(0xffffffffu, mx1, o));
        }
        float mn0 = fmaxf(m0, mx0), mn1 = fmaxf(m1, mx1);
        float sc0 = __expf(m0 - mn0), sc1 = __expf(m1 - mn1);
        m0 = mn0; m1 = mn1;

        float sum0 = 0.f, sum1 = 0.f;
        #pragma unroll
        for (int nf = 0; nf < 16; nf++) {
            float p0 = __expf(acc[nf][0] - mn0);
            float p1 = __expf(acc[nf][1] - mn0);
            float p2 = __expf(acc[nf][2] - mn1);
            float p3 = __expf(acc[nf][3] - mn1);
            acc[nf][0]=p0; acc[nf][1]=p1; acc[nf][2]=p2; acc[nf][3]=p3;
            sum0 += p0 + p1; sum1 += p2 + p3;
        }
        #pragma unroll
        for (int o = 1; o <= 2; o <<= 1) {
            sum0 += __shfl_xor_sync(0xffffffffu, sum0, o);
            sum1 += __shfl_xor_sync(0xffffffffu, sum1, o);
        }
        l0 = l0*sc0 + sum0; l1 = l1*sc1 + sum1;

        #pragma unroll
        for (int onf = 0; onf < 8; onf++) {
            oacc[onf][0]*=sc0; oacc[onf][1]*=sc0;
            oacc[onf][2]*=sc1; oacc[onf][3]*=sc1;
        }

        #pragma unroll
        for (int g = 0; g < 8; g++) {
            uint32_t pah[4], pal[4];
            {
                float v00=acc[2*g][0], v01=acc[2*g][1], v02=acc[2*g][2], v03=acc[2*g][3];
                float w00=acc[2*g+1][0], w01=acc[2*g+1][1], w02=acc[2*g+1][2], w03=acc[2*g+1][3];
                __nv_bfloat16 h00=__float2bfloat16(v00), h01=__float2bfloat16(v01);
                __nv_bfloat16 h02=__float2bfloat16(v02), h03=__float2bfloat16(v03);
                __nv_bfloat16 k00=__float2bfloat16(w00), k01=__float2bfloat16(w01);
                __nv_bfloat16 k02=__float2bfloat16(w02), k03=__float2bfloat16(w03);
                pah[0]=pk(h00,h01); pah[1]=pk(h02,h03); pah[2]=pk(k00,k01); pah[3]=pk(k02,k03);
                pal[0]=pk(__float2bfloat16(v00-__bfloat162float(h00)),
                          __float2bfloat16(v01-__bfloat162float(h01)));
                pal[1]=pk(__float2bfloat16(v02-__bfloat162float(h02)),
                          __float2bfloat16(v03-__bfloat162float(h03)));
                pal[2]=pk(__float2bfloat16(w00-__bfloat162float(k00)),
                          __float2bfloat16(w01-__bfloat162float(k01)));
                pal[3]=pk(__float2bfloat16(w02-__bfloat162float(k02)),
                          __float2bfloat16(w03-__bfloat162float(k03)));
            }
            #pragma unroll
            for (int p = 0; p < 4; p++) {
                int off = ((g*16 + vKrow) * QP + p*16 + vNoff) * 2;
                uint32_t th[4], tl[4];
                ldsm4t(th, bVh + off);
                ldsm4t(tl, bVl + off);
                mma3(oacc[2*p  ], pah, pal, &th[0], &tl[0]);
                mma3(oacc[2*p+1], pah, pal, &th[2], &tl[2]);
            }
        }
        __syncthreads();
    }

    float inv0 = 1.f / l0, inv1 = 1.f / l1;
    #pragma unroll
    for (int onf = 0; onf < 8; onf++) {
        int col = h*HDm + onf*8 + cq*2;
        size_t o0 = (size_t)(b*NN + row0) * DD + col;
        size_t o1 = (size_t)(b*NN + row1) * DD + col;
        *(float2*)&O[o0] = make_float2(oacc[onf][0]*inv0, oacc[onf][1]*inv0);
        *(float2*)&O[o1] = make_float2(oacc[onf][2]*inv1, oacc[onf][3]*inv1);
    }
}

// ---------------- launch ----------------
extern "C" void kernel_launch(void* const* d_in, const int* in_sizes, int n_in,
                              void* d_out, int out_size) {
    const float* x      = (const float*)d_in[0];
    const int*   mask   = (const int*)  d_in[1];
    const float* inter  = (const float*)d_in[2];
    const float* w_qkv  = (const float*)d_in[3];
    const float* b_qkv  = (const float*)d_in[4];
    const float* w_out  = (const float*)d_in[5];
    const float* b_out  = (const float*)d_in[6];
    const float* w1     = (const float*)d_in[7];
    const float* b1     = (const float*)d_in[8];
    const float* w2     = (const float*)d_in[9];
    const float* b2     = (const float*)d_in[10];
    const float* g_pre  = (const float*)d_in[11];
    const float* be_pre = (const float*)d_in[12];
    const float* g_post = (const float*)d_in[13];
    const float* be_post= (const float*)d_in[14];
    const float* g_ffn  = (const float*)d_in[15];
    const float* be_ffn = (const float*)d_in[16];
    const float* g_mid  = (const float*)d_in[17];
    const float* be_mid = (const float*)d_in[18];
    float* out = (float*)d_out;

    float *H, *QKV, *IT, *O, *O2, *ATT, *F, *F1;
    cudaGetSymbolAddress((void**)&H,   g_H);
    cudaGetSymbolAddress((void**)&QKV, g_QKV);
    cudaGetSymbolAddress((void**)&IT,  g_IT);
    cudaGetSymbolAddress((void**)&O,   g_O);
    cudaGetSymbolAddress((void**)&O2,  g_O2);
    cudaGetSymbolAddress((void**)&ATT, g_ATT);
    cudaGetSymbolAddress((void**)&F,   g_F);
    cudaGetSymbolAddress((void**)&F1,  g_F1);

    static bool attr_set = false;
    if (!attr_set) {
        cudaFuncSetAttribute(attn_fused, cudaFuncAttributeMaxDynamicSharedMemorySize,
                             4*128*QP*2);
        attr_set = true;
    }

    // interaction transpose + mask fold (independent of LN/QKV chain)
    inter_tr_kernel<<<dim3(NN, BB), 256>>>(inter, mask, IT);

    ln512_kernel<<<ROWS, 128>>>(x, g_pre, be_pre, H);
    gemm_bf3<1><<<dim3(QKVW/128, ROWS/128), 256>>>(H, w_qkv, b_qkv, nullptr, QKV,
                                                   DD, DD, QKVW, QKVW);
    attn_fused<<<dim3(4, BB*HH), 256, 4*128*QP*2>>>(QKV, IT, O);
    gemm_bf3<1><<<dim3(DD/128, ROWS/128), 256>>>(O, w_out, b_out, nullptr, O2,
                                                 DD, DD, DD, DD);
    ln_post_kernel<<<ROWS, 128>>>(O2, x, g_post, be_post, g_ffn, be_ffn, ATT, F);
    gemm_bf3<2><<<dim3(ED/128, ROWS/128), 256>>>(F, w1, b1, nullptr, F1,
                                                 DD, DD, ED, ED);
    ln_mid_kernel<<<ROWS, 128>>>(F1, g_mid, be_mid);
    gemm_bf3<3><<<dim3(DD/128, ROWS/128), 256>>>(F1, w2, b2, ATT, out,
                                                 ED, ED, DD, DD);
}